// round 1
// baseline (speedup 1.0000x reference)
#include <cuda_runtime.h>
#include <cstdint>
#include <cstddef>

#define B_  4
#define T_  2048
#define D_  1024
#define H_  16
#define HD_ 64

// Static device scratch (allocation-free rule): q,k,v in [B,H,T,HD], attn out in [B,T,D]
__device__ float g_q [(size_t)B_ * H_ * T_ * HD_];
__device__ float g_k [(size_t)B_ * H_ * T_ * HD_];
__device__ float g_v [(size_t)B_ * H_ * T_ * HD_];
__device__ float g_ao[(size_t)B_ * T_ * D_];

__device__ __forceinline__ unsigned f2tf(float x) {
    unsigned u;
    asm("cvt.rna.tf32.f32 %0, %1;" : "=r"(u) : "f"(x));
    return u;
}

// D += A*B with m16n8k8 tf32, fp32 accum. d is the 4-reg C/D fragment.
__device__ __forceinline__ void mma8(float* d, const unsigned* a, const unsigned* b) {
    asm volatile(
        "mma.sync.aligned.m16n8k8.row.col.f32.tf32.tf32.f32 "
        "{%0,%1,%2,%3},{%4,%5,%6,%7},{%8,%9},{%0,%1,%2,%3};"
        : "+f"(d[0]), "+f"(d[1]), "+f"(d[2]), "+f"(d[3])
        : "r"(a[0]), "r"(a[1]), "r"(a[2]), "r"(a[3]),
          "r"(b[0]), "r"(b[1]));
}

// ---------------------------------------------------------------------------
// GEMM: C[M=8192, N=1024] = A[8192,1024] @ W[1024,1024]^T + bias
// MODE 0: plain row-major output. MODE 1: scatter to [B,H,T,HD].
// Block tile 128x128, K-tile 16, 256 threads (8 warps, 2m x 4n, warp 64x32).
// ---------------------------------------------------------------------------
template <int MODE>
__global__ void __launch_bounds__(256)
gemm_tf32_kernel(const float* __restrict__ A, const float* __restrict__ W,
                 const float* __restrict__ bias, float* __restrict__ C) {
    __shared__ unsigned As[128 * 20];
    __shared__ unsigned Bs[128 * 20];

    const int tid  = threadIdx.x;
    const int lane = tid & 31;
    const int warp = tid >> 5;
    const int wm   = warp & 1;   // 0..1 -> 64-row stripe
    const int wn   = warp >> 1;  // 0..3 -> 32-col stripe
    const int g    = lane >> 2;  // group id 0..7
    const int t    = lane & 3;   // thread-in-group 0..3

    const int bm = blockIdx.x * 128;
    const int bn = blockIdx.y * 128;

    const int lr = tid >> 1;         // 0..127 (row within tile for loads)
    const int lc = (tid & 1) * 8;    // 0 or 8 (col offset, 8 floats)

    float acc[4][4][4];
#pragma unroll
    for (int i = 0; i < 4; i++)
#pragma unroll
        for (int j = 0; j < 4; j++)
#pragma unroll
            for (int k = 0; k < 4; k++) acc[i][j][k] = 0.f;

    const float* Arow = A + (size_t)(bm + lr) * 1024 + lc;
    const float* Wrow = W + (size_t)(bn + lr) * 1024 + lc;
    unsigned* ap = As + lr * 20 + lc;
    unsigned* bp = Bs + lr * 20 + lc;

    for (int k0 = 0; k0 < 1024; k0 += 16) {
        __syncthreads();
        float4 a0 = *(const float4*)(Arow + k0);
        float4 a1 = *(const float4*)(Arow + k0 + 4);
        float4 w0 = *(const float4*)(Wrow + k0);
        float4 w1 = *(const float4*)(Wrow + k0 + 4);
        ap[0] = f2tf(a0.x); ap[1] = f2tf(a0.y); ap[2] = f2tf(a0.z); ap[3] = f2tf(a0.w);
        ap[4] = f2tf(a1.x); ap[5] = f2tf(a1.y); ap[6] = f2tf(a1.z); ap[7] = f2tf(a1.w);
        bp[0] = f2tf(w0.x); bp[1] = f2tf(w0.y); bp[2] = f2tf(w0.z); bp[3] = f2tf(w0.w);
        bp[4] = f2tf(w1.x); bp[5] = f2tf(w1.y); bp[6] = f2tf(w1.z); bp[7] = f2tf(w1.w);
        __syncthreads();

#pragma unroll
        for (int ks = 0; ks < 16; ks += 8) {
            unsigned af[4][4];
            unsigned bf[4][2];
#pragma unroll
            for (int mt = 0; mt < 4; mt++) {
                const unsigned* p  = As + (wm * 64 + mt * 16 + g) * 20 + ks + t;
                const unsigned* p2 = p + 8 * 20;
                af[mt][0] = p[0];  af[mt][2] = p[4];
                af[mt][1] = p2[0]; af[mt][3] = p2[4];
            }
#pragma unroll
            for (int nt = 0; nt < 4; nt++) {
                const unsigned* p = Bs + (wn * 32 + nt * 8 + g) * 20 + ks + t;
                bf[nt][0] = p[0]; bf[nt][1] = p[4];
            }
#pragma unroll
            for (int mt = 0; mt < 4; mt++)
#pragma unroll
                for (int nt = 0; nt < 4; nt++)
                    mma8(acc[mt][nt], af[mt], bf[nt]);
        }
    }

    // Epilogue
#pragma unroll
    for (int mt = 0; mt < 4; mt++) {
        const int r0 = bm + wm * 64 + mt * 16 + g;
#pragma unroll
        for (int nt = 0; nt < 4; nt++) {
            const int c0 = bn + wn * 32 + nt * 8 + 2 * t;
            const float bv0 = bias[c0];
            const float bv1 = bias[c0 + 1];
            const float v00 = acc[mt][nt][0] + bv0;
            const float v01 = acc[mt][nt][1] + bv1;
            const float v10 = acc[mt][nt][2] + bv0;
            const float v11 = acc[mt][nt][3] + bv1;
            if (MODE == 0) {
                C[(size_t)r0 * 1024 + c0]           = v00;
                C[(size_t)r0 * 1024 + c0 + 1]       = v01;
                C[(size_t)(r0 + 8) * 1024 + c0]     = v10;
                C[(size_t)(r0 + 8) * 1024 + c0 + 1] = v11;
            } else {
                const int bb = r0 >> 11;             // row -> batch (T=2048)
                const int t0 = r0 & 2047;
                const int t1 = (r0 + 8) & 2047;      // +8 never crosses batch (rows mod 16 aligned)
                const int hh = c0 >> 6;
                const int hd = c0 & 63;
                const size_t i0 = (((size_t)(bb * H_ + hh)) * T_ + t0) * HD_ + hd;
                const size_t i1 = (((size_t)(bb * H_ + hh)) * T_ + t1) * HD_ + hd;
                C[i0] = v00; C[i0 + 1] = v01;
                C[i1] = v10; C[i1 + 1] = v11;
            }
        }
    }
}

// ---------------------------------------------------------------------------
// Flash attention (tf32): grid (T/64, B*H), 128 threads (4 warps).
// Warp w owns q-rows [w*16, w*16+16). Online softmax in C-fragment registers.
// ---------------------------------------------------------------------------
__global__ void __launch_bounds__(128)
attn_kernel(const unsigned char* __restrict__ mask, float* __restrict__ AO) {
    extern __shared__ unsigned sm[];
    unsigned* Qs = sm;                 // [64][72]
    unsigned* Ks = sm + 64 * 72;       // [64][72]
    unsigned* Vs = sm + 2 * 64 * 72;   // [64][72]
    unsigned* Ps = sm + 3 * 64 * 72;   // [64][72]

    const int tid  = threadIdx.x;
    const int lane = tid & 31;
    const int w    = tid >> 5;
    const int g    = lane >> 2;
    const int t    = lane & 3;

    const int bh = blockIdx.y;
    const int b  = bh >> 4;
    const int h  = bh & 15;
    const int q0 = blockIdx.x * 64;

    const float* qg = g_q + ((size_t)bh * T_ + q0) * HD_;
    const float* kg = g_k + (size_t)bh * T_ * HD_;
    const float* vg = g_v + (size_t)bh * T_ * HD_;

    // Load Q tile once, pre-scaled by 1/sqrt(HD) = 0.125
    {
        const int r = tid >> 1;
        const int c = (tid & 1) * 32;
        const float4* src = (const float4*)(qg + r * 64 + c);
        unsigned* dst = Qs + r * 72 + c;
#pragma unroll
        for (int i = 0; i < 8; i++) {
            float4 v = src[i];
            dst[i * 4 + 0] = f2tf(v.x * 0.125f);
            dst[i * 4 + 1] = f2tf(v.y * 0.125f);
            dst[i * 4 + 2] = f2tf(v.z * 0.125f);
            dst[i * 4 + 3] = f2tf(v.w * 0.125f);
        }
    }

    float o[8][4];
#pragma unroll
    for (int i = 0; i < 8; i++)
#pragma unroll
        for (int j = 0; j < 4; j++) o[i][j] = 0.f;

    float m0 = -1e30f, m1 = -1e30f, l0 = 0.f, l1 = 0.f;

    const size_t mrow0 = ((size_t)b * T_ + q0 + w * 16 + g) * T_;
    const size_t mrow1 = mrow0 + (size_t)8 * T_;

    for (int kt = 0; kt < T_; kt += 64) {
        __syncthreads();
        {
            const int r = tid >> 1;
            const int c = (tid & 1) * 32;
            const float4* ksrc = (const float4*)(kg + (size_t)(kt + r) * 64 + c);
            const float4* vsrc = (const float4*)(vg + (size_t)(kt + r) * 64 + c);
            unsigned* kd = Ks + r * 72 + c;
            unsigned* vd = Vs + r * 72 + c;
#pragma unroll
            for (int i = 0; i < 8; i++) {
                float4 kv = ksrc[i];
                float4 vv = vsrc[i];
                kd[i * 4 + 0] = f2tf(kv.x); kd[i * 4 + 1] = f2tf(kv.y);
                kd[i * 4 + 2] = f2tf(kv.z); kd[i * 4 + 3] = f2tf(kv.w);
                vd[i * 4 + 0] = f2tf(vv.x); vd[i * 4 + 1] = f2tf(vv.y);
                vd[i * 4 + 2] = f2tf(vv.z); vd[i * 4 + 3] = f2tf(vv.w);
            }
        }
        __syncthreads();

        // S = Q @ K^T  (per warp: 16 x 64)
        float s[8][4];
#pragma unroll
        for (int i = 0; i < 8; i++)
#pragma unroll
            for (int j = 0; j < 4; j++) s[i][j] = 0.f;

#pragma unroll
        for (int ks = 0; ks < 8; ks++) {
            unsigned a[4];
            const unsigned* p = Qs + (w * 16 + g) * 72 + ks * 8 + t;
            a[0] = p[0]; a[2] = p[4];
            a[1] = p[8 * 72]; a[3] = p[8 * 72 + 4];
#pragma unroll
            for (int nt = 0; nt < 8; nt++) {
                unsigned bb[2];
                const unsigned* pb = Ks + (nt * 8 + g) * 72 + ks * 8 + t;
                bb[0] = pb[0]; bb[1] = pb[4];
                mma8(s[nt], a, bb);
            }
        }

        // Apply mask (bool, true => -inf)
        {
            const unsigned short* mr0 = (const unsigned short*)(mask + mrow0 + kt);
            const unsigned short* mr1 = (const unsigned short*)(mask + mrow1 + kt);
#pragma unroll
            for (int nt = 0; nt < 8; nt++) {
                const int ui = nt * 4 + t;  // ushort index = (nt*8 + 2t)/2
                const unsigned short mm0 = mr0[ui];
                const unsigned short mm1 = mr1[ui];
                if (mm0 & 0xff) s[nt][0] = -1e30f;
                if (mm0 >> 8)   s[nt][1] = -1e30f;
                if (mm1 & 0xff) s[nt][2] = -1e30f;
                if (mm1 >> 8)   s[nt][3] = -1e30f;
            }
        }

        // Row max over this thread's cols, then across the 4 lanes of the row
        float rm0 = -1e30f, rm1 = -1e30f;
#pragma unroll
        for (int nt = 0; nt < 8; nt++) {
            rm0 = fmaxf(rm0, fmaxf(s[nt][0], s[nt][1]));
            rm1 = fmaxf(rm1, fmaxf(s[nt][2], s[nt][3]));
        }
        rm0 = fmaxf(rm0, __shfl_xor_sync(0xffffffffu, rm0, 1));
        rm0 = fmaxf(rm0, __shfl_xor_sync(0xffffffffu, rm0, 2));
        rm1 = fmaxf(rm1, __shfl_xor_sync(0xffffffffu, rm1, 1));
        rm1 = fmaxf(rm1, __shfl_xor_sync(0xffffffffu, rm1, 2));

        const float mn0 = fmaxf(m0, rm0);
        const float mn1 = fmaxf(m1, rm1);
        const float al0 = __expf(m0 - mn0);
        const float al1 = __expf(m1 - mn1);
        m0 = mn0; m1 = mn1;

        float rs0 = 0.f, rs1 = 0.f;
        unsigned* pw = Ps + (w * 16 + g) * 72;
#pragma unroll
        for (int nt = 0; nt < 8; nt++) {
            const float p0 = __expf(s[nt][0] - mn0);
            const float p1 = __expf(s[nt][1] - mn0);
            const float p2 = __expf(s[nt][2] - mn1);
            const float p3 = __expf(s[nt][3] - mn1);
            rs0 += p0 + p1;
            rs1 += p2 + p3;
            const int c = nt * 8 + 2 * t;
            pw[c]            = f2tf(p0);
            pw[c + 1]        = f2tf(p1);
            pw[8 * 72 + c]     = f2tf(p2);
            pw[8 * 72 + c + 1] = f2tf(p3);
        }
        rs0 += __shfl_xor_sync(0xffffffffu, rs0, 1);
        rs0 += __shfl_xor_sync(0xffffffffu, rs0, 2);
        rs1 += __shfl_xor_sync(0xffffffffu, rs1, 1);
        rs1 += __shfl_xor_sync(0xffffffffu, rs1, 2);

        l0 = l0 * al0 + rs0;
        l1 = l1 * al1 + rs1;
#pragma unroll
        for (int nt = 0; nt < 8; nt++) {
            o[nt][0] *= al0; o[nt][1] *= al0;
            o[nt][2] *= al1; o[nt][3] *= al1;
        }

        __syncwarp();  // Ps stripe written by this warp, read by this warp

        // O += P @ V
#pragma unroll
        for (int ks = 0; ks < 8; ks++) {
            unsigned a[4];
            const unsigned* p = Ps + (w * 16 + g) * 72 + ks * 8 + t;
            a[0] = p[0]; a[2] = p[4];
            a[1] = p[8 * 72]; a[3] = p[8 * 72 + 4];
#pragma unroll
            for (int nt = 0; nt < 8; nt++) {
                unsigned bb[2];
                const unsigned* pb = Vs + (ks * 8 + t) * 72 + nt * 8 + g;
                bb[0] = pb[0]; bb[1] = pb[4 * 72];
                mma8(o[nt], a, bb);
            }
        }
    }

    // Epilogue: normalize and scatter to [B, T, H*HD]
    const float inv0 = 1.f / l0;
    const float inv1 = 1.f / l1;
    const int qr = q0 + w * 16 + g;
    float* out0 = AO + ((size_t)b * T_ + qr) * D_ + h * 64;
    float* out1 = out0 + (size_t)8 * D_;
#pragma unroll
    for (int nt = 0; nt < 8; nt++) {
        const int c = nt * 8 + 2 * t;
        out0[c]     = o[nt][0] * inv0;
        out0[c + 1] = o[nt][1] * inv0;
        out1[c]     = o[nt][2] * inv1;
        out1[c + 1] = o[nt][3] * inv1;
    }
}

extern "C" void kernel_launch(void* const* d_in, const int* in_sizes, int n_in,
                              void* d_out, int out_size) {
    const float* query = (const float*)d_in[0];
    const float* key_  = (const float*)d_in[1];
    const float* value = (const float*)d_in[2];
    const unsigned char* mask = (const unsigned char*)d_in[3];
    const float* Wq = (const float*)d_in[4];
    const float* bq = (const float*)d_in[5];
    const float* Wk = (const float*)d_in[6];
    const float* bk = (const float*)d_in[7];
    const float* Wv = (const float*)d_in[8];
    const float* bv = (const float*)d_in[9];
    const float* Wo = (const float*)d_in[10];
    const float* bo = (const float*)d_in[11];

    void *pq, *pk, *pv, *pao;
    cudaGetSymbolAddress(&pq, g_q);
    cudaGetSymbolAddress(&pk, g_k);
    cudaGetSymbolAddress(&pv, g_v);
    cudaGetSymbolAddress(&pao, g_ao);

    cudaFuncSetAttribute(attn_kernel,
                         cudaFuncAttributeMaxDynamicSharedMemorySize, 73728);

    dim3 gemm_grid(64, 8);
    gemm_tf32_kernel<1><<<gemm_grid, 256>>>(query, Wq, bq, (float*)pq);
    gemm_tf32_kernel<1><<<gemm_grid, 256>>>(key_,  Wk, bk, (float*)pk);
    gemm_tf32_kernel<1><<<gemm_grid, 256>>>(value, Wv, bv, (float*)pv);

    attn_kernel<<<dim3(32, 64), 128, 73728>>>(mask, (float*)pao);

    gemm_tf32_kernel<0><<<gemm_grid, 256>>>((const float*)pao, Wo, bo, (float*)d_out);
}

// round 2
// speedup vs baseline: 1.1562x; 1.1562x over previous
#include <cuda_runtime.h>
#include <cstdint>
#include <cstddef>

#define B_  4
#define T_  2048
#define D_  1024
#define H_  16
#define HD_ 64

// Static device scratch: q,k,v in [B,H,T,HD], attn out in [B,T,D]
__device__ float g_q [(size_t)B_ * H_ * T_ * HD_];
__device__ float g_k [(size_t)B_ * H_ * T_ * HD_];
__device__ float g_v [(size_t)B_ * H_ * T_ * HD_];
__device__ float g_ao[(size_t)B_ * T_ * D_];

__device__ __forceinline__ unsigned f2tf(float x) {
    unsigned u;
    asm("cvt.rna.tf32.f32 %0, %1;" : "=r"(u) : "f"(x));
    return u;
}
__device__ __forceinline__ float ex2(float x) {
    float y;
    asm("ex2.approx.f32 %0, %1;" : "=f"(y) : "f"(x));
    return y;
}

// D += A*B with m16n8k8 tf32, fp32 accum.
__device__ __forceinline__ void mma8(float* d, const unsigned* a, const unsigned* b) {
    asm volatile(
        "mma.sync.aligned.m16n8k8.row.col.f32.tf32.tf32.f32 "
        "{%0,%1,%2,%3},{%4,%5,%6,%7},{%8,%9},{%0,%1,%2,%3};"
        : "+f"(d[0]), "+f"(d[1]), "+f"(d[2]), "+f"(d[3])
        : "r"(a[0]), "r"(a[1]), "r"(a[2]), "r"(a[3]),
          "r"(b[0]), "r"(b[1]));
}

// Interleave one k-group of 8 (two float4: k0..3, k4..7) into two uint4 with
// element k stored at position (k&3)*2 + (k>>2)  ->  pairs (t, t+4) adjacent.
__device__ __forceinline__ void ilv(float4 a, float4 b, uint4& u0, uint4& u1) {
    u0.x = f2tf(a.x); u0.y = f2tf(b.x); u0.z = f2tf(a.y); u0.w = f2tf(b.y);
    u1.x = f2tf(a.z); u1.y = f2tf(b.z); u1.z = f2tf(a.w); u1.w = f2tf(b.w);
}
__device__ __forceinline__ void ilv_scaled(float4 a, float4 b, float sc, uint4& u0, uint4& u1) {
    u0.x = f2tf(a.x * sc); u0.y = f2tf(b.x * sc); u0.z = f2tf(a.y * sc); u0.w = f2tf(b.y * sc);
    u1.x = f2tf(a.z * sc); u1.y = f2tf(b.z * sc); u1.z = f2tf(a.w * sc); u1.w = f2tf(b.w * sc);
}

// ---------------------------------------------------------------------------
// GEMM: C[8192,1024] = A @ W^T + bias. 128x128 tile, K-tile 16, 256 threads.
// Double-buffered smem (2 stages), k-interleaved layout, LDS.64 fragments.
// Smem stride 24 words (conflict-free fragment loads).
// MODE 0: row-major out. MODE 1: scatter to [B,H,T,HD].
// ---------------------------------------------------------------------------
#define GS 24          // smem row stride in words
#define GTILE (128*GS) // words per tile buffer

template <int MODE>
__global__ void __launch_bounds__(256)
gemm_tf32_kernel(const float* __restrict__ A, const float* __restrict__ W,
                 const float* __restrict__ bias, float* __restrict__ C) {
    extern __shared__ unsigned gsm[];
    unsigned* Abuf[2] = { gsm,             gsm + 2 * GTILE };
    unsigned* Bbuf[2] = { gsm + GTILE,     gsm + 3 * GTILE };

    const int tid  = threadIdx.x;
    const int lane = tid & 31;
    const int warp = tid >> 5;
    const int wm   = warp & 1;
    const int wn   = warp >> 1;
    const int g    = lane >> 2;
    const int t    = lane & 3;

    const int bm = blockIdx.x * 128;
    const int bn = blockIdx.y * 128;

    const int lr = tid >> 1;       // 0..127
    const int lc = (tid & 1) * 8;  // k-group base: 0 or 8

    float acc[4][4][4];
#pragma unroll
    for (int i = 0; i < 4; i++)
#pragma unroll
        for (int j = 0; j < 4; j++)
#pragma unroll
            for (int k = 0; k < 4; k++) acc[i][j][k] = 0.f;

    const float* Arow = A + (size_t)(bm + lr) * 1024 + lc;
    const float* Wrow = W + (size_t)(bn + lr) * 1024 + lc;

    // Prologue: load tile 0 into stage 0
    {
        float4 a0 = *(const float4*)(Arow);
        float4 a1 = *(const float4*)(Arow + 4);
        float4 w0 = *(const float4*)(Wrow);
        float4 w1 = *(const float4*)(Wrow + 4);
        uint4 u0, u1;
        ilv(a0, a1, u0, u1);
        *(uint4*)(Abuf[0] + lr * GS + lc)     = u0;
        *(uint4*)(Abuf[0] + lr * GS + lc + 4) = u1;
        ilv(w0, w1, u0, u1);
        *(uint4*)(Bbuf[0] + lr * GS + lc)     = u0;
        *(uint4*)(Bbuf[0] + lr * GS + lc + 4) = u1;
    }
    __syncthreads();

    for (int it = 0; it < 64; ++it) {
        const int cur = it & 1;

        // Prefetch next tile into registers (latency hidden behind MMAs)
        float4 na0, na1, nw0, nw1;
        if (it < 63) {
            const int kn = (it + 1) * 16;
            na0 = *(const float4*)(Arow + kn);
            na1 = *(const float4*)(Arow + kn + 4);
            nw0 = *(const float4*)(Wrow + kn);
            nw1 = *(const float4*)(Wrow + kn + 4);
        }

        const unsigned* Ac = Abuf[cur];
        const unsigned* Bc = Bbuf[cur];
#pragma unroll
        for (int ks = 0; ks < 16; ks += 8) {
            unsigned af[4][4];
            unsigned bf[4][2];
#pragma unroll
            for (int mt = 0; mt < 4; mt++) {
                uint2 lo = *(const uint2*)(Ac + (wm * 64 + mt * 16 + g) * GS + ks + 2 * t);
                uint2 hi = *(const uint2*)(Ac + (wm * 64 + mt * 16 + 8 + g) * GS + ks + 2 * t);
                af[mt][0] = lo.x; af[mt][1] = hi.x; af[mt][2] = lo.y; af[mt][3] = hi.y;
            }
#pragma unroll
            for (int nt = 0; nt < 4; nt++) {
                uint2 bb = *(const uint2*)(Bc + (wn * 32 + nt * 8 + g) * GS + ks + 2 * t);
                bf[nt][0] = bb.x; bf[nt][1] = bb.y;
            }
#pragma unroll
            for (int mt = 0; mt < 4; mt++)
#pragma unroll
                for (int nt = 0; nt < 4; nt++)
                    mma8(acc[mt][nt], af[mt], bf[nt]);
        }

        if (it < 63) {
            uint4 u0, u1;
            ilv(na0, na1, u0, u1);
            *(uint4*)(Abuf[cur ^ 1] + lr * GS + lc)     = u0;
            *(uint4*)(Abuf[cur ^ 1] + lr * GS + lc + 4) = u1;
            ilv(nw0, nw1, u0, u1);
            *(uint4*)(Bbuf[cur ^ 1] + lr * GS + lc)     = u0;
            *(uint4*)(Bbuf[cur ^ 1] + lr * GS + lc + 4) = u1;
        }
        __syncthreads();
    }

    // Epilogue
#pragma unroll
    for (int mt = 0; mt < 4; mt++) {
        const int r0 = bm + wm * 64 + mt * 16 + g;
#pragma unroll
        for (int nt = 0; nt < 4; nt++) {
            const int c0 = bn + wn * 32 + nt * 8 + 2 * t;
            const float bv0 = bias[c0];
            const float bv1 = bias[c0 + 1];
            const float v00 = acc[mt][nt][0] + bv0;
            const float v01 = acc[mt][nt][1] + bv1;
            const float v10 = acc[mt][nt][2] + bv0;
            const float v11 = acc[mt][nt][3] + bv1;
            if (MODE == 0) {
                *(float2*)&C[(size_t)r0 * 1024 + c0]       = make_float2(v00, v01);
                *(float2*)&C[(size_t)(r0 + 8) * 1024 + c0] = make_float2(v10, v11);
            } else {
                const int bb = r0 >> 11;
                const int t0 = r0 & 2047;
                const int t1 = (r0 + 8) & 2047;
                const int hh = c0 >> 6;
                const int hd = c0 & 63;
                const size_t i0 = (((size_t)(bb * H_ + hh)) * T_ + t0) * HD_ + hd;
                const size_t i1 = (((size_t)(bb * H_ + hh)) * T_ + t1) * HD_ + hd;
                *(float2*)&C[i0] = make_float2(v00, v01);
                *(float2*)&C[i1] = make_float2(v10, v11);
            }
        }
    }
}

// ---------------------------------------------------------------------------
// Flash attention (tf32): Q-tile 128, K-tile 64, 128 threads (4 warps).
// Warp owns 32 q-rows (2 m-fragments) -> K/V b-fragments reused 2x.
// Q/K smem k-interleaved (LDS.64 fragments); V natural; P natural.
// Smem row stride 72 words. exp via ex2 with log2e folded into Q scale.
// ---------------------------------------------------------------------------
#define AS 72  // attn smem row stride (words)

__global__ void __launch_bounds__(128)
attn_kernel(const unsigned char* __restrict__ mask, float* __restrict__ AO) {
    extern __shared__ unsigned sm[];
    unsigned* Qs = sm;                    // 128 x AS
    unsigned* Ks = sm + 128 * AS;         // 64 x AS
    unsigned* Vs = Ks + 64 * AS;          // 64 x AS
    unsigned* Ps = Vs + 64 * AS;          // 128 x AS

    const int tid  = threadIdx.x;
    const int lane = tid & 31;
    const int w    = tid >> 5;
    const int g    = lane >> 2;
    const int t    = lane & 3;

    const int bh = blockIdx.y;
    const int b  = bh >> 4;
    const int h  = bh & 15;
    const int q0 = blockIdx.x * 128;

    const float* qg = g_q + ((size_t)bh * T_ + q0) * HD_;
    const float* kg = g_k + (size_t)bh * T_ * HD_;
    const float* vg = g_v + (size_t)bh * T_ * HD_;

    // Load Q tile (128x64), scaled by 1/sqrt(HD) * log2(e), interleaved
    {
        const float SC = 0.125f * 1.44269504088896340736f;
        const float4* src = (const float4*)(qg + (size_t)tid * 64);
        unsigned* dst = Qs + tid * AS;
#pragma unroll
        for (int jg = 0; jg < 8; ++jg) {
            float4 x0 = src[2 * jg];
            float4 x1 = src[2 * jg + 1];
            uint4 u0, u1;
            ilv_scaled(x0, x1, SC, u0, u1);
            *(uint4*)(dst + jg * 8)     = u0;
            *(uint4*)(dst + jg * 8 + 4) = u1;
        }
    }

    float o[2][8][4];
#pragma unroll
    for (int mt = 0; mt < 2; mt++)
#pragma unroll
        for (int i = 0; i < 8; i++)
#pragma unroll
            for (int j = 0; j < 4; j++) o[mt][i][j] = 0.f;

    float mx[2][2], lsum[2][2];
#pragma unroll
    for (int mt = 0; mt < 2; mt++) {
        mx[mt][0] = -1e30f; mx[mt][1] = -1e30f;
        lsum[mt][0] = 0.f;  lsum[mt][1] = 0.f;
    }

    for (int kt = 0; kt < T_; kt += 64) {
        __syncthreads();
        // Load K (interleaved) and V (natural), both with RNA tf32 conversion
        {
            const int r = tid >> 1;
            const int c = (tid & 1) * 32;
            const float4* ksrc = (const float4*)(kg + (size_t)(kt + r) * 64 + c);
            const float4* vsrc = (const float4*)(vg + (size_t)(kt + r) * 64 + c);
            unsigned* kd = Ks + r * AS + c;
            unsigned* vd = Vs + r * AS + c;
#pragma unroll
            for (int jg = 0; jg < 4; ++jg) {
                float4 k0 = ksrc[2 * jg];
                float4 k1 = ksrc[2 * jg + 1];
                uint4 u0, u1;
                ilv(k0, k1, u0, u1);
                *(uint4*)(kd + jg * 8)     = u0;
                *(uint4*)(kd + jg * 8 + 4) = u1;
                float4 v0 = vsrc[2 * jg];
                float4 v1 = vsrc[2 * jg + 1];
                uint4 w0, w1;
                w0.x = f2tf(v0.x); w0.y = f2tf(v0.y); w0.z = f2tf(v0.z); w0.w = f2tf(v0.w);
                w1.x = f2tf(v1.x); w1.y = f2tf(v1.y); w1.z = f2tf(v1.z); w1.w = f2tf(v1.w);
                *(uint4*)(vd + jg * 8)     = w0;
                *(uint4*)(vd + jg * 8 + 4) = w1;
            }
        }
        __syncthreads();

        // S = Q @ K^T : per warp 32 x 64
        float s[2][8][4];
#pragma unroll
        for (int mt = 0; mt < 2; mt++)
#pragma unroll
            for (int i = 0; i < 8; i++)
#pragma unroll
                for (int j = 0; j < 4; j++) s[mt][i][j] = 0.f;

#pragma unroll
        for (int ks = 0; ks < 8; ks++) {
            unsigned af[2][4];
#pragma unroll
            for (int mt = 0; mt < 2; mt++) {
                uint2 lo = *(const uint2*)(Qs + (w * 32 + mt * 16 + g) * AS + ks * 8 + 2 * t);
                uint2 hi = *(const uint2*)(Qs + (w * 32 + mt * 16 + 8 + g) * AS + ks * 8 + 2 * t);
                af[mt][0] = lo.x; af[mt][1] = hi.x; af[mt][2] = lo.y; af[mt][3] = hi.y;
            }
#pragma unroll
            for (int nt = 0; nt < 8; nt++) {
                uint2 bb = *(const uint2*)(Ks + (nt * 8 + g) * AS + ks * 8 + 2 * t);
                unsigned bf[2] = { bb.x, bb.y };
                mma8(s[0][nt], af[0], bf);
                mma8(s[1][nt], af[1], bf);
            }
        }

        // Mask (bool, true => -inf)
#pragma unroll
        for (int mt = 0; mt < 2; mt++) {
            const size_t mr = ((size_t)b * T_ + q0 + w * 32 + mt * 16 + g) * T_ + kt;
            const unsigned short* m0p = (const unsigned short*)(mask + mr);
            const unsigned short* m1p = (const unsigned short*)(mask + mr + (size_t)8 * T_);
#pragma unroll
            for (int nt = 0; nt < 8; nt++) {
                const unsigned short ma = m0p[nt * 4 + t];
                const unsigned short mb = m1p[nt * 4 + t];
                if (ma & 0xff) s[mt][nt][0] = -1e30f;
                if (ma >> 8)   s[mt][nt][1] = -1e30f;
                if (mb & 0xff) s[mt][nt][2] = -1e30f;
                if (mb >> 8)   s[mt][nt][3] = -1e30f;
            }
        }

        // Online softmax (log2 domain) + P store
#pragma unroll
        for (int mt = 0; mt < 2; mt++) {
            float rm0 = -1e30f, rm1 = -1e30f;
#pragma unroll
            for (int nt = 0; nt < 8; nt++) {
                rm0 = fmaxf(rm0, fmaxf(s[mt][nt][0], s[mt][nt][1]));
                rm1 = fmaxf(rm1, fmaxf(s[mt][nt][2], s[mt][nt][3]));
            }
            rm0 = fmaxf(rm0, __shfl_xor_sync(0xffffffffu, rm0, 1));
            rm0 = fmaxf(rm0, __shfl_xor_sync(0xffffffffu, rm0, 2));
            rm1 = fmaxf(rm1, __shfl_xor_sync(0xffffffffu, rm1, 1));
            rm1 = fmaxf(rm1, __shfl_xor_sync(0xffffffffu, rm1, 2));

            const float mn0 = fmaxf(mx[mt][0], rm0);
            const float mn1 = fmaxf(mx[mt][1], rm1);
            const float al0 = ex2(mx[mt][0] - mn0);
            const float al1 = ex2(mx[mt][1] - mn1);
            mx[mt][0] = mn0; mx[mt][1] = mn1;

            float rs0 = 0.f, rs1 = 0.f;
            unsigned* pw = Ps + (w * 32 + mt * 16 + g) * AS;
#pragma unroll
            for (int nt = 0; nt < 8; nt++) {
                const float p0 = ex2(s[mt][nt][0] - mn0);
                const float p1 = ex2(s[mt][nt][1] - mn0);
                const float p2 = ex2(s[mt][nt][2] - mn1);
                const float p3 = ex2(s[mt][nt][3] - mn1);
                rs0 += p0 + p1;
                rs1 += p2 + p3;
                uint2 u;
                u.x = f2tf(p0); u.y = f2tf(p1);
                *(uint2*)(pw + nt * 8 + 2 * t) = u;
                u.x = f2tf(p2); u.y = f2tf(p3);
                *(uint2*)(pw + 8 * AS + nt * 8 + 2 * t) = u;
            }
            rs0 += __shfl_xor_sync(0xffffffffu, rs0, 1);
            rs0 += __shfl_xor_sync(0xffffffffu, rs0, 2);
            rs1 += __shfl_xor_sync(0xffffffffu, rs1, 1);
            rs1 += __shfl_xor_sync(0xffffffffu, rs1, 2);

            lsum[mt][0] = lsum[mt][0] * al0 + rs0;
            lsum[mt][1] = lsum[mt][1] * al1 + rs1;
#pragma unroll
            for (int nt = 0; nt < 8; nt++) {
                o[mt][nt][0] *= al0; o[mt][nt][1] *= al0;
                o[mt][nt][2] *= al1; o[mt][nt][3] *= al1;
            }
        }

        __syncwarp();  // Ps stripe is warp-private

        // O += P @ V
#pragma unroll
        for (int ks = 0; ks < 8; ks++) {
            unsigned af[2][4];
#pragma unroll
            for (int mt = 0; mt < 2; mt++) {
                const unsigned* pa = Ps + (w * 32 + mt * 16 + g) * AS + ks * 8 + t;
                af[mt][0] = pa[0];
                af[mt][1] = pa[8 * AS];
                af[mt][2] = pa[4];
                af[mt][3] = pa[8 * AS + 4];
            }
#pragma unroll
            for (int nt = 0; nt < 8; nt++) {
                const unsigned* pb = Vs + (ks * 8 + t) * AS + nt * 8 + g;
                unsigned bf[2] = { pb[0], pb[4 * AS] };
                mma8(o[0][nt], af[0], bf);
                mma8(o[1][nt], af[1], bf);
            }
        }
    }

    // Epilogue: normalize and scatter to [B, T, H*HD]
#pragma unroll
    for (int mt = 0; mt < 2; mt++) {
        const float inv0 = 1.f / lsum[mt][0];
        const float inv1 = 1.f / lsum[mt][1];
        const int qr = q0 + w * 32 + mt * 16 + g;
        float* out0 = AO + ((size_t)b * T_ + qr) * D_ + h * 64;
        float* out1 = out0 + (size_t)8 * D_;
#pragma unroll
        for (int nt = 0; nt < 8; nt++) {
            const int c = nt * 8 + 2 * t;
            *(float2*)(out0 + c) = make_float2(o[mt][nt][0] * inv0, o[mt][nt][1] * inv0);
            *(float2*)(out1 + c) = make_float2(o[mt][nt][2] * inv1, o[mt][nt][3] * inv1);
        }
    }
}

extern "C" void kernel_launch(void* const* d_in, const int* in_sizes, int n_in,
                              void* d_out, int out_size) {
    const float* query = (const float*)d_in[0];
    const float* key_  = (const float*)d_in[1];
    const float* value = (const float*)d_in[2];
    const unsigned char* mask = (const unsigned char*)d_in[3];
    const float* Wq = (const float*)d_in[4];
    const float* bq = (const float*)d_in[5];
    const float* Wk = (const float*)d_in[6];
    const float* bk = (const float*)d_in[7];
    const float* Wv = (const float*)d_in[8];
    const float* bv = (const float*)d_in[9];
    const float* Wo = (const float*)d_in[10];
    const float* bo = (const float*)d_in[11];

    void *pq, *pk, *pv, *pao;
    cudaGetSymbolAddress(&pq, g_q);
    cudaGetSymbolAddress(&pk, g_k);
    cudaGetSymbolAddress(&pv, g_v);
    cudaGetSymbolAddress(&pao, g_ao);

    const int gemm_smem = 4 * GTILE * 4;   // 49152 B
    const int attn_smem = (128 + 64 + 64 + 128) * AS * 4;  // 110592 B
    cudaFuncSetAttribute(gemm_tf32_kernel<0>,
                         cudaFuncAttributeMaxDynamicSharedMemorySize, gemm_smem);
    cudaFuncSetAttribute(gemm_tf32_kernel<1>,
                         cudaFuncAttributeMaxDynamicSharedMemorySize, gemm_smem);
    cudaFuncSetAttribute(attn_kernel,
                         cudaFuncAttributeMaxDynamicSharedMemorySize, attn_smem);

    dim3 gemm_grid(64, 8);
    gemm_tf32_kernel<1><<<gemm_grid, 256, gemm_smem>>>(query, Wq, bq, (float*)pq);
    gemm_tf32_kernel<1><<<gemm_grid, 256, gemm_smem>>>(key_,  Wk, bk, (float*)pk);
    gemm_tf32_kernel<1><<<gemm_grid, 256, gemm_smem>>>(value, Wv, bv, (float*)pv);

    attn_kernel<<<dim3(16, 64), 128, attn_smem>>>(mask, (float*)pao);

    gemm_tf32_kernel<0><<<gemm_grid, 256, gemm_smem>>>((const float*)pao, Wo, bo, (float*)d_out);
}

// round 3
// speedup vs baseline: 1.4066x; 1.2166x over previous
#include <cuda_runtime.h>
#include <cstdint>
#include <cstddef>

#define B_  4
#define T_  2048
#define D_  1024
#define H_  16
#define HD_ 64

// Static scratch. g_q/g_k: tf32 bits, [B,H,T,HD], hd k-interleaved (Q pre-scaled).
// g_v: tf32 bits, TRANSPOSED [B,H,HD,T], token-interleaved. g_ao: float [B,T,D].
__device__ unsigned g_q [(size_t)B_ * H_ * T_ * HD_];
__device__ unsigned g_k [(size_t)B_ * H_ * T_ * HD_];
__device__ unsigned g_v [(size_t)B_ * H_ * HD_ * T_];
__device__ float    g_ao[(size_t)B_ * T_ * D_];

__device__ __forceinline__ unsigned f2tf(float x) {
    unsigned u;
    asm("cvt.rna.tf32.f32 %0, %1;" : "=r"(u) : "f"(x));
    return u;
}
__device__ __forceinline__ float ex2(float x) {
    float y;
    asm("ex2.approx.f32 %0, %1;" : "=f"(y) : "f"(x));
    return y;
}
// interleave low-3-bits: k -> (k&3)*2 + (k>>2)   (pairs (t,t+4) adjacent)
__device__ __forceinline__ int ilvc(int x) {
    return (x & ~7) | (((x & 3) << 1) | ((x & 7) >> 2));
}

__device__ __forceinline__ void mma8(float* d, const unsigned* a, const unsigned* b) {
    asm volatile(
        "mma.sync.aligned.m16n8k8.row.col.f32.tf32.tf32.f32 "
        "{%0,%1,%2,%3},{%4,%5,%6,%7},{%8,%9},{%0,%1,%2,%3};"
        : "+f"(d[0]), "+f"(d[1]), "+f"(d[2]), "+f"(d[3])
        : "r"(a[0]), "r"(a[1]), "r"(a[2]), "r"(a[3]),
          "r"(b[0]), "r"(b[1]));
}

__device__ __forceinline__ void ilv(float4 a, float4 b, uint4& u0, uint4& u1) {
    u0.x = f2tf(a.x); u0.y = f2tf(b.x); u0.z = f2tf(a.y); u0.w = f2tf(b.y);
    u1.x = f2tf(a.z); u1.y = f2tf(b.z); u1.z = f2tf(a.w); u1.w = f2tf(b.w);
}

#define CPA16(dst, src) asm volatile("cp.async.cg.shared.global [%0], [%1], 16;" :: "r"(dst), "l"(src))
#define CPCOMMIT()      asm volatile("cp.async.commit_group;")
#define CPWAIT(n)       asm volatile("cp.async.wait_group %0;" :: "n"(n))

// ---------------------------------------------------------------------------
// GEMM: C[8192,1024] = A @ W^T + bias. 128x128 tile, K-tile 16, 256 threads,
// double-buffered. MODE 0: float row-major.  MODE 1: Q (tf32, scaled,
// interleaved, [B,H,T,HD]).  MODE 2: K (same, unscaled).  MODE 3: V^T
// (tf32, [B,H,HD,T], token-interleaved).
// ---------------------------------------------------------------------------
#define GS 24
#define GTILE (128*GS)

template <int MODE>
__global__ void __launch_bounds__(256, 2)
gemm_tf32_kernel(const float* __restrict__ A, const float* __restrict__ W,
                 const float* __restrict__ bias, float* __restrict__ C) {
    extern __shared__ unsigned gsm[];
    unsigned* Abuf[2] = { gsm,         gsm + 2 * GTILE };
    unsigned* Bbuf[2] = { gsm + GTILE, gsm + 3 * GTILE };

    const int tid  = threadIdx.x;
    const int lane = tid & 31;
    const int warp = tid >> 5;
    const int wm   = warp & 1;
    const int wn   = warp >> 1;
    const int g    = lane >> 2;
    const int t    = lane & 3;

    const int bm = blockIdx.x * 128;
    const int bn = blockIdx.y * 128;

    const int lr = tid >> 1;
    const int lc = (tid & 1) * 8;

    float acc[4][4][4];
#pragma unroll
    for (int i = 0; i < 4; i++)
#pragma unroll
        for (int j = 0; j < 4; j++)
#pragma unroll
            for (int k = 0; k < 4; k++) acc[i][j][k] = 0.f;

    const float* Arow = A + (size_t)(bm + lr) * 1024 + lc;
    const float* Wrow = W + (size_t)(bn + lr) * 1024 + lc;

    {
        float4 a0 = *(const float4*)(Arow);
        float4 a1 = *(const float4*)(Arow + 4);
        float4 w0 = *(const float4*)(Wrow);
        float4 w1 = *(const float4*)(Wrow + 4);
        uint4 u0, u1;
        ilv(a0, a1, u0, u1);
        *(uint4*)(Abuf[0] + lr * GS + lc)     = u0;
        *(uint4*)(Abuf[0] + lr * GS + lc + 4) = u1;
        ilv(w0, w1, u0, u1);
        *(uint4*)(Bbuf[0] + lr * GS + lc)     = u0;
        *(uint4*)(Bbuf[0] + lr * GS + lc + 4) = u1;
    }
    __syncthreads();

    for (int it = 0; it < 64; ++it) {
        const int cur = it & 1;
        float4 na0, na1, nw0, nw1;
        if (it < 63) {
            const int kn = (it + 1) * 16;
            na0 = *(const float4*)(Arow + kn);
            na1 = *(const float4*)(Arow + kn + 4);
            nw0 = *(const float4*)(Wrow + kn);
            nw1 = *(const float4*)(Wrow + kn + 4);
        }

        const unsigned* Ac = Abuf[cur];
        const unsigned* Bc = Bbuf[cur];
#pragma unroll
        for (int ks = 0; ks < 16; ks += 8) {
            unsigned af[4][4];
            unsigned bf[4][2];
#pragma unroll
            for (int mt = 0; mt < 4; mt++) {
                uint2 lo = *(const uint2*)(Ac + (wm * 64 + mt * 16 + g) * GS + ks + 2 * t);
                uint2 hi = *(const uint2*)(Ac + (wm * 64 + mt * 16 + 8 + g) * GS + ks + 2 * t);
                af[mt][0] = lo.x; af[mt][1] = hi.x; af[mt][2] = lo.y; af[mt][3] = hi.y;
            }
#pragma unroll
            for (int nt = 0; nt < 4; nt++) {
                uint2 bb = *(const uint2*)(Bc + (wn * 32 + nt * 8 + g) * GS + ks + 2 * t);
                bf[nt][0] = bb.x; bf[nt][1] = bb.y;
            }
#pragma unroll
            for (int mt = 0; mt < 4; mt++)
#pragma unroll
                for (int nt = 0; nt < 4; nt++)
                    mma8(acc[mt][nt], af[mt], bf[nt]);
        }

        if (it < 63) {
            uint4 u0, u1;
            ilv(na0, na1, u0, u1);
            *(uint4*)(Abuf[cur ^ 1] + lr * GS + lc)     = u0;
            *(uint4*)(Abuf[cur ^ 1] + lr * GS + lc + 4) = u1;
            ilv(nw0, nw1, u0, u1);
            *(uint4*)(Bbuf[cur ^ 1] + lr * GS + lc)     = u0;
            *(uint4*)(Bbuf[cur ^ 1] + lr * GS + lc + 4) = u1;
        }
        __syncthreads();
    }

    const float SC = 0.18033688011112042f;  // 0.125 * log2(e)

#pragma unroll
    for (int mt = 0; mt < 4; mt++) {
        const int r0 = bm + wm * 64 + mt * 16 + g;
#pragma unroll
        for (int nt = 0; nt < 4; nt++) {
            const int c0 = bn + wn * 32 + nt * 8 + 2 * t;
            const float bv0 = bias[c0];
            const float bv1 = bias[c0 + 1];
            float v00 = acc[mt][nt][0] + bv0;
            float v01 = acc[mt][nt][1] + bv1;
            float v10 = acc[mt][nt][2] + bv0;
            float v11 = acc[mt][nt][3] + bv1;
            if (MODE == 0) {
                *(float2*)&C[(size_t)r0 * 1024 + c0]       = make_float2(v00, v01);
                *(float2*)&C[(size_t)(r0 + 8) * 1024 + c0] = make_float2(v10, v11);
            } else {
                const int bb  = r0 >> 11;
                const int hh  = c0 >> 6;
                const int hd0 = c0 & 63;
                const int t0  = r0 & 2047;
                const int t1  = (r0 + 8) & 2047;
                if (MODE == 1 || MODE == 2) {
                    if (MODE == 1) { v00 *= SC; v01 *= SC; v10 *= SC; v11 *= SC; }
                    const size_t base = (size_t)(bb * H_ + hh) * T_;
                    const size_t i0 = (base + t0) * HD_;
                    const size_t i1 = (base + t1) * HD_;
                    const int cA = ilvc(hd0), cB = ilvc(hd0 + 1);
                    C[i0 + cA] = __uint_as_float(f2tf(v00));
                    C[i0 + cB] = __uint_as_float(f2tf(v01));
                    C[i1 + cA] = __uint_as_float(f2tf(v10));
                    C[i1 + cB] = __uint_as_float(f2tf(v11));
                } else {  // MODE 3: V^T [B,H,HD,T], token-interleaved
                    const size_t base = (size_t)(bb * H_ + hh) * HD_;
                    const size_t j0 = (base + hd0) * T_;
                    const size_t j1 = (base + hd0 + 1) * T_;
                    const int tA = ilvc(t0), tB = ilvc(t1);
                    C[j0 + tA] = __uint_as_float(f2tf(v00));
                    C[j1 + tA] = __uint_as_float(f2tf(v01));
                    C[j0 + tB] = __uint_as_float(f2tf(v10));
                    C[j1 + tB] = __uint_as_float(f2tf(v11));
                }
            }
        }
    }
}

// ---------------------------------------------------------------------------
// Flash attention: Q-tile 128, K-tile 64, 4 warps. Operands pre-converted in
// gmem; K/V tiles via cp.async double buffer; P via quad shuffles (no smem).
// ---------------------------------------------------------------------------
#define AS 72

__global__ void __launch_bounds__(128, 2)
attn_kernel(const unsigned* __restrict__ Qg, const unsigned* __restrict__ Kg,
            const unsigned* __restrict__ Vg, const unsigned char* __restrict__ mask,
            float* __restrict__ AO) {
    extern __shared__ unsigned sm[];
    unsigned* Qs = sm;                        // 128 x AS
    unsigned* Kb[2] = { sm + 128 * AS,          sm + (128 + 128) * AS };
    unsigned* Vb[2] = { sm + (128 + 64) * AS,   sm + (128 + 192) * AS };

    const int tid  = threadIdx.x;
    const int lane = tid & 31;
    const int w    = tid >> 5;
    const int g    = lane >> 2;
    const int t    = lane & 3;

    const int bh = blockIdx.y;
    const int b  = bh >> 4;
    const int h  = bh & 15;
    const int q0 = blockIdx.x * 128;

    const unsigned* qg = Qg + ((size_t)bh * T_ + q0) * HD_;
    const unsigned* kg = Kg + (size_t)bh * T_ * HD_;
    const unsigned* vg = Vg + (size_t)bh * HD_ * T_;

    const unsigned smbase = (unsigned)__cvta_generic_to_shared(sm);
    const unsigned Qs_u = smbase;
    const unsigned Kb_u[2] = { smbase + 128 * AS * 4, smbase + 256 * AS * 4 };
    const unsigned Vb_u[2] = { smbase + 192 * AS * 4, smbase + 320 * AS * 4 };

    // Q tile: 64 words per thread
    {
        const unsigned* src = qg + (size_t)tid * 64;
        const unsigned dst = Qs_u + tid * AS * 4;
#pragma unroll
        for (int j = 0; j < 16; j++) CPA16(dst + j * 16, src + j * 4);
    }
    // tile 0 K/V
    {
        const int r  = tid >> 1;
        const int cb = (tid & 1) * 32;
        const unsigned* ks = kg + (size_t)r * 64 + cb;
        const unsigned* vs = vg + (size_t)r * T_ + cb;
        const unsigned kd = Kb_u[0] + (r * AS + cb) * 4;
        const unsigned vd = Vb_u[0] + (r * AS + cb) * 4;
#pragma unroll
        for (int j = 0; j < 8; j++) { CPA16(kd + j * 16, ks + j * 4); CPA16(vd + j * 16, vs + j * 4); }
    }
    CPCOMMIT();

    float o[2][8][4];
#pragma unroll
    for (int mt = 0; mt < 2; mt++)
#pragma unroll
        for (int i = 0; i < 8; i++)
#pragma unroll
            for (int j = 0; j < 4; j++) o[mt][i][j] = 0.f;

    float mx[2][2], lsum[2][2];
#pragma unroll
    for (int mt = 0; mt < 2; mt++) {
        mx[mt][0] = -1e30f; mx[mt][1] = -1e30f;
        lsum[mt][0] = 0.f;  lsum[mt][1] = 0.f;
    }

    const int sl0 = (lane & ~3) | (t >> 1);
    const int sl1 = sl0 + 2;

    for (int it = 0; it < 32; ++it) {
        const int cur = it & 1;
        if (it < 31) {
            const int kt = (it + 1) * 64;
            const int r  = tid >> 1;
            const int cb = (tid & 1) * 32;
            const unsigned* ks = kg + (size_t)r * 64 + (size_t)kt * 64 + cb;
            const unsigned* vs = vg + (size_t)r * T_ + kt + cb;
            const unsigned kd = Kb_u[cur ^ 1] + (r * AS + cb) * 4;
            const unsigned vd = Vb_u[cur ^ 1] + (r * AS + cb) * 4;
#pragma unroll
            for (int j = 0; j < 8; j++) { CPA16(kd + j * 16, ks + j * 4); CPA16(vd + j * 16, vs + j * 4); }
            CPCOMMIT();
            CPWAIT(1);
        } else {
            CPWAIT(0);
        }
        __syncthreads();

        const unsigned* Kc = Kb[cur];
        const unsigned* Vc = Vb[cur];
        const int kt = it * 64;

        // S = Q @ K^T
        float s[2][8][4];
#pragma unroll
        for (int mt = 0; mt < 2; mt++)
#pragma unroll
            for (int i = 0; i < 8; i++)
#pragma unroll
                for (int j = 0; j < 4; j++) s[mt][i][j] = 0.f;

#pragma unroll
        for (int ks = 0; ks < 8; ks++) {
            unsigned af[2][4];
#pragma unroll
            for (int mt = 0; mt < 2; mt++) {
                uint2 lo = *(const uint2*)(Qs + (w * 32 + mt * 16 + g) * AS + ks * 8 + 2 * t);
                uint2 hi = *(const uint2*)(Qs + (w * 32 + mt * 16 + 8 + g) * AS + ks * 8 + 2 * t);
                af[mt][0] = lo.x; af[mt][1] = hi.x; af[mt][2] = lo.y; af[mt][3] = hi.y;
            }
#pragma unroll
            for (int nt = 0; nt < 8; nt++) {
                uint2 bb2 = *(const uint2*)(Kc + (nt * 8 + g) * AS + ks * 8 + 2 * t);
                unsigned bf[2] = { bb2.x, bb2.y };
                mma8(s[0][nt], af[0], bf);
                mma8(s[1][nt], af[1], bf);
            }
        }

        // Mask
#pragma unroll
        for (int mt = 0; mt < 2; mt++) {
            const size_t mr = ((size_t)b * T_ + q0 + w * 32 + mt * 16 + g) * T_ + kt;
            const unsigned short* m0p = (const unsigned short*)(mask + mr);
            const unsigned short* m1p = (const unsigned short*)(mask + mr + (size_t)8 * T_);
#pragma unroll
            for (int nt = 0; nt < 8; nt++) {
                const unsigned short ma = m0p[nt * 4 + t];
                const unsigned short mb = m1p[nt * 4 + t];
                if (ma & 0xff) s[mt][nt][0] = -1e30f;
                if (ma >> 8)   s[mt][nt][1] = -1e30f;
                if (mb & 0xff) s[mt][nt][2] = -1e30f;
                if (mb >> 8)   s[mt][nt][3] = -1e30f;
            }
        }

        // Online softmax (log2 domain); p stored back into s as tf32 bits
#pragma unroll
        for (int mt = 0; mt < 2; mt++) {
            float rm0 = -1e30f, rm1 = -1e30f;
#pragma unroll
            for (int nt = 0; nt < 8; nt++) {
                rm0 = fmaxf(rm0, fmaxf(s[mt][nt][0], s[mt][nt][1]));
                rm1 = fmaxf(rm1, fmaxf(s[mt][nt][2], s[mt][nt][3]));
            }
            rm0 = fmaxf(rm0, __shfl_xor_sync(0xffffffffu, rm0, 1));
            rm0 = fmaxf(rm0, __shfl_xor_sync(0xffffffffu, rm0, 2));
            rm1 = fmaxf(rm1, __shfl_xor_sync(0xffffffffu, rm1, 1));
            rm1 = fmaxf(rm1, __shfl_xor_sync(0xffffffffu, rm1, 2));

            const float mn0 = fmaxf(mx[mt][0], rm0);
            const float mn1 = fmaxf(mx[mt][1], rm1);
            const float al0 = ex2(mx[mt][0] - mn0);
            const float al1 = ex2(mx[mt][1] - mn1);
            mx[mt][0] = mn0; mx[mt][1] = mn1;

            float rs0 = 0.f, rs1 = 0.f;
#pragma unroll
            for (int nt = 0; nt < 8; nt++) {
                const float p0 = ex2(s[mt][nt][0] - mn0);
                const float p1 = ex2(s[mt][nt][1] - mn0);
                const float p2 = ex2(s[mt][nt][2] - mn1);
                const float p3 = ex2(s[mt][nt][3] - mn1);
                rs0 += p0 + p1;
                rs1 += p2 + p3;
                s[mt][nt][0] = __uint_as_float(f2tf(p0));
                s[mt][nt][1] = __uint_as_float(f2tf(p1));
                s[mt][nt][2] = __uint_as_float(f2tf(p2));
                s[mt][nt][3] = __uint_as_float(f2tf(p3));
            }
            rs0 += __shfl_xor_sync(0xffffffffu, rs0, 1);
            rs0 += __shfl_xor_sync(0xffffffffu, rs0, 2);
            rs1 += __shfl_xor_sync(0xffffffffu, rs1, 1);
            rs1 += __shfl_xor_sync(0xffffffffu, rs1, 2);

            lsum[mt][0] = lsum[mt][0] * al0 + rs0;
            lsum[mt][1] = lsum[mt][1] * al1 + rs1;
#pragma unroll
            for (int nt = 0; nt < 8; nt++) {
                o[mt][nt][0] *= al0; o[mt][nt][1] *= al0;
                o[mt][nt][2] *= al1; o[mt][nt][3] *= al1;
            }
        }

        // O += P @ V : A-fragments built from p via quad shuffles
#pragma unroll
        for (int ks = 0; ks < 8; ks++) {
            unsigned af[2][4];
#pragma unroll
            for (int mt = 0; mt < 2; mt++) {
                const unsigned p0 = __float_as_uint(s[mt][ks][0]);
                const unsigned p1 = __float_as_uint(s[mt][ks][1]);
                const unsigned p2 = __float_as_uint(s[mt][ks][2]);
                const unsigned p3 = __float_as_uint(s[mt][ks][3]);
                const unsigned x0 = __shfl_sync(0xffffffffu, p0, sl0);
                const unsigned x1 = __shfl_sync(0xffffffffu, p1, sl0);
                const unsigned y0 = __shfl_sync(0xffffffffu, p0, sl1);
                const unsigned y1 = __shfl_sync(0xffffffffu, p1, sl1);
                af[mt][0] = (t & 1) ? x1 : x0;
                af[mt][2] = (t & 1) ? y1 : y0;
                const unsigned z0 = __shfl_sync(0xffffffffu, p2, sl0);
                const unsigned z1 = __shfl_sync(0xffffffffu, p3, sl0);
                const unsigned u0 = __shfl_sync(0xffffffffu, p2, sl1);
                const unsigned u1 = __shfl_sync(0xffffffffu, p3, sl1);
                af[mt][1] = (t & 1) ? z1 : z0;
                af[mt][3] = (t & 1) ? u1 : u0;
            }
#pragma unroll
            for (int nt = 0; nt < 8; nt++) {
                uint2 bb2 = *(const uint2*)(Vc + (nt * 8 + g) * AS + ks * 8 + 2 * t);
                unsigned bf[2] = { bb2.x, bb2.y };
                mma8(o[0][nt], af[0], bf);
                mma8(o[1][nt], af[1], bf);
            }
        }
        __syncthreads();
    }

    // Epilogue
#pragma unroll
    for (int mt = 0; mt < 2; mt++) {
        const float inv0 = 1.f / lsum[mt][0];
        const float inv1 = 1.f / lsum[mt][1];
        const int qr = q0 + w * 32 + mt * 16 + g;
        float* out0 = AO + ((size_t)b * T_ + qr) * D_ + h * 64;
        float* out1 = out0 + (size_t)8 * D_;
#pragma unroll
        for (int nt = 0; nt < 8; nt++) {
            const int c = nt * 8 + 2 * t;
            *(float2*)(out0 + c) = make_float2(o[mt][nt][0] * inv0, o[mt][nt][1] * inv0);
            *(float2*)(out1 + c) = make_float2(o[mt][nt][2] * inv1, o[mt][nt][3] * inv1);
        }
    }
}

extern "C" void kernel_launch(void* const* d_in, const int* in_sizes, int n_in,
                              void* d_out, int out_size) {
    const float* query = (const float*)d_in[0];
    const float* key_  = (const float*)d_in[1];
    const float* value = (const float*)d_in[2];
    const unsigned char* mask = (const unsigned char*)d_in[3];
    const float* Wq = (const float*)d_in[4];
    const float* bq = (const float*)d_in[5];
    const float* Wk = (const float*)d_in[6];
    const float* bk = (const float*)d_in[7];
    const float* Wv = (const float*)d_in[8];
    const float* bv = (const float*)d_in[9];
    const float* Wo = (const float*)d_in[10];
    const float* bo = (const float*)d_in[11];

    void *pq, *pk, *pv, *pao;
    cudaGetSymbolAddress(&pq, g_q);
    cudaGetSymbolAddress(&pk, g_k);
    cudaGetSymbolAddress(&pv, g_v);
    cudaGetSymbolAddress(&pao, g_ao);

    const int gemm_smem = 4 * GTILE * 4;                   // 49152
    const int attn_smem = (128 + 256) * AS * 4;            // 110592
    cudaFuncSetAttribute(gemm_tf32_kernel<0>, cudaFuncAttributeMaxDynamicSharedMemorySize, gemm_smem);
    cudaFuncSetAttribute(gemm_tf32_kernel<1>, cudaFuncAttributeMaxDynamicSharedMemorySize, gemm_smem);
    cudaFuncSetAttribute(gemm_tf32_kernel<2>, cudaFuncAttributeMaxDynamicSharedMemorySize, gemm_smem);
    cudaFuncSetAttribute(gemm_tf32_kernel<3>, cudaFuncAttributeMaxDynamicSharedMemorySize, gemm_smem);
    cudaFuncSetAttribute(attn_kernel, cudaFuncAttributeMaxDynamicSharedMemorySize, attn_smem);

    dim3 gemm_grid(64, 8);
    gemm_tf32_kernel<1><<<gemm_grid, 256, gemm_smem>>>(query, Wq, bq, (float*)pq);
    gemm_tf32_kernel<2><<<gemm_grid, 256, gemm_smem>>>(key_,  Wk, bk, (float*)pk);
    gemm_tf32_kernel<3><<<gemm_grid, 256, gemm_smem>>>(value, Wv, bv, (float*)pv);

    attn_kernel<<<dim3(16, 64), 128, attn_smem>>>(
        (const unsigned*)pq, (const unsigned*)pk, (const unsigned*)pv, mask, (float*)pao);

    gemm_tf32_kernel<0><<<gemm_grid, 256, gemm_smem>>>((const float*)pao, Wo, bo, (float*)d_out);
}